// round 4
// baseline (speedup 1.0000x reference)
#include <cuda_runtime.h>
#include <cstdint>

#define NMAX   100000
#define EHMAX  1600000
#define HD     32          // hidden dim (Hemb == Hgcn == 32)
#define NIN    128

// ---------------- device scratch (no allocations allowed) ----------------
__device__ __align__(16) float g_h  [NMAX * HD];   // relu(x@We + be)
__device__ __align__(16) float g_hw [NMAX * HD];   // dis * (h@Wg)   (dis-scaled!)
__device__ __align__(16) float g_agg[NMAX * HD];   // scatter target
__device__ float g_att [EHMAX];                    // per-undirected-edge attention
__device__ float g_deno[NMAX];
__device__ float g_z   [NMAX];
__device__ float g_dis [NMAX];                     // first deg, then rsqrt(deg+1)
__device__ unsigned g_amax_u;                      // ordered-uint encoded global max

// ordered monotone float<->uint mapping for atomicMax on floats
__device__ __forceinline__ unsigned henc(float f) {
    unsigned u = __float_as_uint(f);
    return (u & 0x80000000u) ? ~u : (u | 0x80000000u);
}
__device__ __forceinline__ float hdec(unsigned e) {
    return (e & 0x80000000u) ? __uint_as_float(e ^ 0x80000000u)
                             : __uint_as_float(~e);
}

// ---------------- K0: init ----------------
__global__ void k_init(int n) {
    int stride = gridDim.x * blockDim.x;
    int tid = blockIdx.x * blockDim.x + threadIdx.x;
    int tot = n * HD;
    for (int i = tid; i < tot; i += stride) g_agg[i] = 0.f;
    for (int i = tid; i < n;   i += stride) { g_deno[i] = 0.f; g_z[i] = 0.f; g_dis[i] = 0.f; }
    if (tid == 0) g_amax_u = 0x007fffffu;  // henc(-inf)
}

// ---------------- K1: fused embed: h = relu(x@We+be); hw = h@Wg --------
// 2 nodes per warp to amortize the W_emb shared loads.
__global__ __launch_bounds__(256) void k_embed(
    const float* __restrict__ x, const float* __restrict__ We,
    const float* __restrict__ be, const float* __restrict__ Wg, int n)
{
    __shared__ float sWe[NIN * HD];
    __shared__ float sWg[HD * HD];
    __shared__ float sbe[HD];
    __shared__ float sx[8][2][NIN];

    int tid = threadIdx.x;
    for (int i = tid; i < NIN * HD; i += 256) sWe[i] = We[i];
    for (int i = tid; i < HD * HD;  i += 256) sWg[i] = Wg[i];
    if (tid < HD) sbe[tid] = be[tid];
    __syncthreads();

    int warp = tid >> 5, j = tid & 31;
    int n0 = (blockIdx.x * 8 + warp) * 2;
    int n1 = n0 + 1;
    bool v0 = n0 < n, v1 = n1 < n;

    if (v0) {
        const float* xr = x + (size_t)n0 * NIN;
        sx[warp][0][j] = xr[j]; sx[warp][0][j+32] = xr[j+32];
        sx[warp][0][j+64] = xr[j+64]; sx[warp][0][j+96] = xr[j+96];
    }
    if (v1) {
        const float* xr = x + (size_t)n1 * NIN;
        sx[warp][1][j] = xr[j]; sx[warp][1][j+32] = xr[j+32];
        sx[warp][1][j+64] = xr[j+64]; sx[warp][1][j+96] = xr[j+96];
    } else {
        // keep garbage out of the unguarded FMA stream
        sx[warp][1][j] = 0.f; sx[warp][1][j+32] = 0.f;
        sx[warp][1][j+64] = 0.f; sx[warp][1][j+96] = 0.f;
    }
    __syncwarp();
    if (!v0) return;

    float a0 = sbe[j], a1 = sbe[j];
    #pragma unroll
    for (int k = 0; k < NIN; k++) {
        float w = sWe[k * HD + j];
        a0 = fmaf(sx[warp][0][k], w, a0);
        a1 = fmaf(sx[warp][1][k], w, a1);
    }
    float h0 = fmaxf(a0, 0.f), h1 = fmaxf(a1, 0.f);
    g_h[n0 * HD + j] = h0;
    if (v1) g_h[n1 * HD + j] = h1;

    float c0 = 0.f, c1 = 0.f;
    #pragma unroll
    for (int k = 0; k < HD; k++) {
        float w = sWg[k * HD + j];
        c0 = fmaf(__shfl_sync(0xffffffffu, h0, k), w, c0);
        c1 = fmaf(__shfl_sync(0xffffffffu, h1, k), w, c1);
    }
    g_hw[n0 * HD + j] = c0;
    if (v1) g_hw[n1 * HD + j] = c1;
}

// ---------------- K2: degree (over symmetric half-edges) ----------------
__global__ void k_deg(const int* __restrict__ row, const int* __restrict__ col, int eh) {
    int e = blockIdx.x * blockDim.x + threadIdx.x;
    if (e >= eh) return;
    atomicAdd(&g_dis[row[e]], 1.f);
    atomicAdd(&g_dis[col[e]], 1.f);
}

// ---------------- K3: dis = rsqrt(deg+1) ----------------
__global__ void k_dis(int n) {
    int i = blockIdx.x * blockDim.x + threadIdx.x;
    if (i < n) g_dis[i] = rsqrtf(g_dis[i] + 1.0f);
}

// ---------------- K4: hw *= dis   (pre-scale messages once per node) ----
__global__ void k_scalehw(int n) {
    int i = blockIdx.x * blockDim.x + threadIdx.x;
    if (i < n * HD) g_hw[i] *= g_dis[i >> 5];
}

// ---------------- K5: att dot + global max ----------------
// 8 threads / edge, 4 edges / 8-thread group. Loads/stores are guarded;
// shuffles are UNCONDITIONAL (convergence-safe regardless of eh).
__global__ __launch_bounds__(256) void k_dot(
    const int* __restrict__ row, const int* __restrict__ col, int eh)
{
    int g   = (blockIdx.x * blockDim.x + threadIdx.x) >> 3;
    int sub = threadIdx.x & 7;
    const float4* h4 = (const float4*)g_h;
    float lmax = -1e30f;
    int base = g * 4;
    #pragma unroll
    for (int q = 0; q < 4; q++) {
        int e = base + q;
        bool valid = (e < eh);
        float4 a = make_float4(0.f, 0.f, 0.f, 0.f);
        float4 b = a;
        if (valid) {
            int s = row[e], d = col[e];
            a = h4[(size_t)s * 8 + sub];
            b = h4[(size_t)d * 8 + sub];
        }
        float p = a.x*b.x + a.y*b.y + a.z*b.z + a.w*b.w;
        p += __shfl_xor_sync(0xffffffffu, p, 4);
        p += __shfl_xor_sync(0xffffffffu, p, 2);
        p += __shfl_xor_sync(0xffffffffu, p, 1);
        if (valid) {
            if (sub == 0) g_att[e] = p;
            lmax = fmaxf(lmax, p);
        }
    }
    __shared__ float sm[256];
    sm[threadIdx.x] = lmax;
    __syncthreads();
    for (int s = 128; s > 0; s >>= 1) {
        if (threadIdx.x < s) sm[threadIdx.x] = fmaxf(sm[threadIdx.x], sm[threadIdx.x + s]);
        __syncthreads();
    }
    if (threadIdx.x == 0) atomicMax(&g_amax_u, henc(sm[0]));
}

// ---------------- K6: exp + denominator ----------------
__global__ void k_expdeno(const int* __restrict__ row, const int* __restrict__ col, int eh) {
    int e = blockIdx.x * blockDim.x + threadIdx.x;
    if (e >= eh) return;
    float amax = hdec(g_amax_u);
    float a = __expf(g_att[e] - amax);
    g_att[e] = a;
    atomicAdd(&g_deno[row[e]], a);   // directed (s,d): row=s
    atomicAdd(&g_deno[col[e]], a);   // directed (d,s): row=d
}

// ---------------- K7: fused z + message scatter (warp per undirected edge)
__global__ __launch_bounds__(256) void k_scatter(
    const int* __restrict__ row, const int* __restrict__ col,
    const float* __restrict__ t, int eh)
{
    int w = (blockIdx.x * blockDim.x + threadIdx.x) >> 5;
    int j = threadIdx.x & 31;
    if (w >= eh) return;
    int s = row[w], d = col[w];
    float ms = g_hw[(size_t)s * HD + j];   // already dis[s]*hw[s]
    float md = g_hw[(size_t)d * HD + j];
    atomicAdd(&g_agg[(size_t)d * HD + j], ms);
    atomicAdd(&g_agg[(size_t)s * HD + j], md);
    if (j == 0) {
        float a = g_att[w];
        atomicAdd(&g_z[s], a / (g_deno[s] + 1e-8f) * t[d]);
        atomicAdd(&g_z[d], a / (g_deno[d] + 1e-8f) * t[s]);
    }
}

// ---------------- K8: gcn + residual + MLP head (warp per node) ----------
__global__ __launch_bounds__(256) void k_final(
    const float* __restrict__ t,
    const float* __restrict__ W1, const float* __restrict__ b1,
    const float* __restrict__ W2, const float* __restrict__ b2,
    const float* __restrict__ b_gcn,
    float* __restrict__ outp, float* __restrict__ repp, float* __restrict__ zoutp,
    int n)
{
    __shared__ float sW1[34 * HD];
    __shared__ float sb1[HD], sW2[HD], sb2s[1];
    int tid = threadIdx.x;
    for (int i = tid; i < 34 * HD; i += 256) sW1[i] = W1[i];
    if (tid < HD) { sb1[tid] = b1[tid]; sW2[tid] = W2[tid]; }
    if (tid == 0) sb2s[0] = b2[0];
    __syncthreads();

    int w = blockIdx.x * 8 + (tid >> 5);
    int j = tid & 31;
    if (w >= n) return;

    float dis  = g_dis[w];
    float dhwv = g_hw [(size_t)w * HD + j];   // dis*hw
    float aggv = g_agg[(size_t)w * HD + j];
    float gcn  = dis * aggv + dis * dhwv + b_gcn[j];  // dis*agg + dis^2*hw + b
    float rep  = g_h[(size_t)w * HD + j] + fmaxf(gcn, 0.f);

    float* rp = repp ? repp : g_agg;         // fallback scratch (in-place safe)
    rp[(size_t)w * HD + j] = rep;

    float ti = t[w];
    float zi = g_z[w];

    float acc = sb1[j];
    #pragma unroll
    for (int k = 0; k < HD; k++)
        acc = fmaf(__shfl_sync(0xffffffffu, rep, k), sW1[k * HD + j], acc);
    acc = fmaf(ti, sW1[32 * HD + j], acc);
    acc = fmaf(zi, sW1[33 * HD + j], acc);
    acc = fmaxf(acc, 0.f);

    float o = acc * sW2[j];
    #pragma unroll
    for (int off = 16; off > 0; off >>= 1)
        o += __shfl_xor_sync(0xffffffffu, o, off);
    if (j == 0) outp[w] = o + sb2s[0];
    if (zoutp && j == 1) zoutp[w] = zi;
}

// ---------------- host ----------------
extern "C" void kernel_launch(void* const* d_in, const int* in_sizes, int n_in,
                              void* d_out, int out_size)
{
    const float* x     = (const float*)d_in[0];
    const float* t     = (const float*)d_in[1];
    const int*   row   = (const int*)  d_in[2];
    const int*   col   = (const int*)  d_in[3];
    const float* W_emb = (const float*)d_in[4];
    const float* b_emb = (const float*)d_in[5];
    const float* W_gcn = (const float*)d_in[6];
    const float* b_gcn = (const float*)d_in[7];
    const float* W1    = (const float*)d_in[8];
    const float* b1    = (const float*)d_in[9];
    const float* W2    = (const float*)d_in[10];
    const float* b2    = (const float*)d_in[11];

    int n  = in_sizes[1];          // t has N elements
    int e2 = in_sizes[2];          // full directed edge count
    int eh = e2 / 2;               // symmetric half

    float* outp = (float*)d_out;
    bool full = (out_size == 34 * n);
    float* repp  = full ? outp + n        : nullptr;
    float* zoutp = full ? outp + 33 * n   : nullptr;

    k_init<<<2048, 256>>>(n);
    k_embed<<<(n + 15) / 16, 256>>>(x, W_emb, b_emb, W_gcn, n);
    k_deg<<<(eh + 255) / 256, 256>>>(row, col, eh);
    k_dis<<<(n + 255) / 256, 256>>>(n);
    k_scalehw<<<(n * HD + 255) / 256, 256>>>(n);
    k_dot<<<(eh + 127) / 128, 256>>>(row, col, eh);
    k_expdeno<<<(eh + 255) / 256, 256>>>(row, col, eh);
    k_scatter<<<(eh + 7) / 8, 256>>>(row, col, t, eh);
    k_final<<<(n + 7) / 8, 256>>>(t, W1, b1, W2, b2, b_gcn, outp, repp, zoutp, n);
}

// round 5
// speedup vs baseline: 1.5170x; 1.5170x over previous
#include <cuda_runtime.h>
#include <cstdint>

#define NMAX   100000
#define EHMAX  1600000
#define HD     32          // hidden dim (Hemb == Hgcn == 32)
#define NIN    128

// ---------------- device scratch (no allocations allowed) ----------------
__device__ __align__(16) float g_h  [NMAX * HD];   // relu(x@We + be)
__device__ __align__(16) float g_hw [NMAX * HD];   // dis * (h@Wg)   (dis-scaled!)
__device__ __align__(16) float g_agg[NMAX * HD];   // scatter target
__device__ float g_att [EHMAX];                    // per-undirected-edge raw dot
__device__ float g_deno[NMAX];
__device__ float g_z   [NMAX];                     // z NUMERATOR (divide in k_final)
__device__ float g_deg [NMAX];
__device__ float g_dis [NMAX];
__device__ unsigned g_amax_u;                      // ordered-uint encoded global max

// ordered monotone float<->uint mapping for atomicMax on floats
__device__ __forceinline__ unsigned henc(float f) {
    unsigned u = __float_as_uint(f);
    return (u & 0x80000000u) ? ~u : (u | 0x80000000u);
}
__device__ __forceinline__ float hdec(unsigned e) {
    return (e & 0x80000000u) ? __uint_as_float(e ^ 0x80000000u)
                             : __uint_as_float(~e);
}

// vectorized 16B reduction (no return) — 1 op replaces 4 scalar REDs
__device__ __forceinline__ void red_add_v4(float* p, float4 v) {
    asm volatile("red.global.add.v4.f32 [%0], {%1, %2, %3, %4};"
                 :: "l"(p), "f"(v.x), "f"(v.y), "f"(v.z), "f"(v.w)
                 : "memory");
}

// ---------------- K0: init ----------------
__global__ void k_init(int n) {
    int stride = gridDim.x * blockDim.x;
    int tid = blockIdx.x * blockDim.x + threadIdx.x;
    int tot = n * HD;
    for (int i = tid; i < tot; i += stride) g_agg[i] = 0.f;
    for (int i = tid; i < n;   i += stride) {
        g_deno[i] = 0.f; g_z[i] = 0.f; g_deg[i] = 0.f;
    }
    if (tid == 0) g_amax_u = 0x007fffffu;  // henc(-inf)
}

// ---------------- K1: fused embed: h = relu(x@We+be); hw = h@Wg --------
__global__ __launch_bounds__(256) void k_embed(
    const float* __restrict__ x, const float* __restrict__ We,
    const float* __restrict__ be, const float* __restrict__ Wg, int n)
{
    __shared__ float sWe[NIN * HD];
    __shared__ float sWg[HD * HD];
    __shared__ float sbe[HD];
    __shared__ float sx[8][2][NIN];

    int tid = threadIdx.x;
    for (int i = tid; i < NIN * HD; i += 256) sWe[i] = We[i];
    for (int i = tid; i < HD * HD;  i += 256) sWg[i] = Wg[i];
    if (tid < HD) sbe[tid] = be[tid];
    __syncthreads();

    int warp = tid >> 5, j = tid & 31;
    int n0 = (blockIdx.x * 8 + warp) * 2;
    int n1 = n0 + 1;
    bool v0 = n0 < n, v1 = n1 < n;

    if (v0) {
        const float* xr = x + (size_t)n0 * NIN;
        sx[warp][0][j] = xr[j]; sx[warp][0][j+32] = xr[j+32];
        sx[warp][0][j+64] = xr[j+64]; sx[warp][0][j+96] = xr[j+96];
    }
    if (v1) {
        const float* xr = x + (size_t)n1 * NIN;
        sx[warp][1][j] = xr[j]; sx[warp][1][j+32] = xr[j+32];
        sx[warp][1][j+64] = xr[j+64]; sx[warp][1][j+96] = xr[j+96];
    } else {
        sx[warp][1][j] = 0.f; sx[warp][1][j+32] = 0.f;
        sx[warp][1][j+64] = 0.f; sx[warp][1][j+96] = 0.f;
    }
    __syncwarp();
    if (!v0) return;

    float a0 = sbe[j], a1 = sbe[j];
    #pragma unroll
    for (int k = 0; k < NIN; k++) {
        float w = sWe[k * HD + j];
        a0 = fmaf(sx[warp][0][k], w, a0);
        a1 = fmaf(sx[warp][1][k], w, a1);
    }
    float h0 = fmaxf(a0, 0.f), h1 = fmaxf(a1, 0.f);
    g_h[n0 * HD + j] = h0;
    if (v1) g_h[n1 * HD + j] = h1;

    float c0 = 0.f, c1 = 0.f;
    #pragma unroll
    for (int k = 0; k < HD; k++) {
        float w = sWg[k * HD + j];
        c0 = fmaf(__shfl_sync(0xffffffffu, h0, k), w, c0);
        c1 = fmaf(__shfl_sync(0xffffffffu, h1, k), w, c1);
    }
    g_hw[n0 * HD + j] = c0;
    if (v1) g_hw[n1 * HD + j] = c1;
}

// ---------------- K2: att dot + global max + degree (fused) -------------
// 8 threads / edge, 4 edges / 8-thread group. Loads/stores guarded;
// shuffles UNCONDITIONAL (convergence-safe regardless of eh).
__global__ __launch_bounds__(256) void k_dotdeg(
    const int* __restrict__ row, const int* __restrict__ col, int eh)
{
    int g   = (blockIdx.x * blockDim.x + threadIdx.x) >> 3;
    int sub = threadIdx.x & 7;
    const float4* h4 = (const float4*)g_h;
    float lmax = -1e30f;
    int base = g * 4;
    #pragma unroll
    for (int q = 0; q < 4; q++) {
        int e = base + q;
        bool valid = (e < eh);
        float4 a = make_float4(0.f, 0.f, 0.f, 0.f);
        float4 b = a;
        int s = 0, d = 0;
        if (valid) {
            s = row[e]; d = col[e];
            a = h4[(size_t)s * 8 + sub];
            b = h4[(size_t)d * 8 + sub];
        }
        float p = a.x*b.x + a.y*b.y + a.z*b.z + a.w*b.w;
        p += __shfl_xor_sync(0xffffffffu, p, 4);
        p += __shfl_xor_sync(0xffffffffu, p, 2);
        p += __shfl_xor_sync(0xffffffffu, p, 1);
        if (valid) {
            if (sub == 0) { g_att[e] = p; atomicAdd(&g_deg[s], 1.f); }
            if (sub == 1) atomicAdd(&g_deg[d], 1.f);
            lmax = fmaxf(lmax, p);
        }
    }
    __shared__ float sm[256];
    sm[threadIdx.x] = lmax;
    __syncthreads();
    for (int s = 128; s > 0; s >>= 1) {
        if (threadIdx.x < s) sm[threadIdx.x] = fmaxf(sm[threadIdx.x], sm[threadIdx.x + s]);
        __syncthreads();
    }
    if (threadIdx.x == 0) atomicMax(&g_amax_u, henc(sm[0]));
}

// ---------------- K3: dis = rsqrt(deg+1); hw *= dis  (one warp = one node)
__global__ void k_disscale(int n) {
    int i = blockIdx.x * blockDim.x + threadIdx.x;   // element index into hw
    if (i >= n * HD) return;
    int node = i >> 5;
    float dis = rsqrtf(g_deg[node] + 1.0f);
    if ((i & 31) == 0) g_dis[node] = dis;
    g_hw[i] *= dis;
}

// ---------------- K4: exp + denominator + z numerator ------------------
__global__ void k_expdeno(const int* __restrict__ row, const int* __restrict__ col,
                          const float* __restrict__ t, int eh) {
    int e = blockIdx.x * blockDim.x + threadIdx.x;
    if (e >= eh) return;
    float amax = hdec(g_amax_u);
    float a = __expf(g_att[e] - amax);
    int s = row[e], d = col[e];
    float ts = t[s], td = t[d];
    atomicAdd(&g_deno[s], a);        // directed (s,d): row=s
    atomicAdd(&g_deno[d], a);        // directed (d,s): row=d
    atomicAdd(&g_z[s], a * td);      // z numerator; /deno deferred to k_final
    atomicAdd(&g_z[d], a * ts);
}

// ---------------- K5: message scatter — 8 lanes/direction, v4 REDs -----
// agg[dst] += dis[src]*hw[src]  for every directed edge (2*eh of them)
__global__ __launch_bounds__(256) void k_scatter(
    const int* __restrict__ row, const int* __restrict__ col, int eh)
{
    int gid = blockIdx.x * blockDim.x + threadIdx.x;
    int dir = gid >> 3;               // directed edge id
    int sub = gid & 7;                // float4 slot within the 32-float row
    if (dir >= 2 * eh) return;
    int e    = dir >> 1;
    int flip = dir & 1;
    int s = row[e], d = col[e];
    int src = flip ? d : s;
    int dst = flip ? s : d;
    const float4* hw4 = (const float4*)g_hw;
    float4 v = hw4[(size_t)src * 8 + sub];          // already dis[src]*hw[src]
    red_add_v4(&g_agg[(size_t)dst * HD + sub * 4], v);
}

// ---------------- K6: gcn + residual + MLP head (warp per node) ----------
__global__ __launch_bounds__(256) void k_final(
    const float* __restrict__ t,
    const float* __restrict__ W1, const float* __restrict__ b1,
    const float* __restrict__ W2, const float* __restrict__ b2,
    const float* __restrict__ b_gcn,
    float* __restrict__ outp, float* __restrict__ repp, float* __restrict__ zoutp,
    int n)
{
    __shared__ float sW1[34 * HD];
    __shared__ float sb1[HD], sW2[HD], sb2s[1];
    int tid = threadIdx.x;
    for (int i = tid; i < 34 * HD; i += 256) sW1[i] = W1[i];
    if (tid < HD) { sb1[tid] = b1[tid]; sW2[tid] = W2[tid]; }
    if (tid == 0) sb2s[0] = b2[0];
    __syncthreads();

    int w = blockIdx.x * 8 + (tid >> 5);
    int j = tid & 31;
    if (w >= n) return;

    float dis  = g_dis[w];
    float dhwv = g_hw [(size_t)w * HD + j];   // dis*hw
    float aggv = g_agg[(size_t)w * HD + j];
    float gcn  = dis * aggv + dis * dhwv + b_gcn[j];  // dis*agg + dis^2*hw + b
    float rep  = g_h[(size_t)w * HD + j] + fmaxf(gcn, 0.f);

    float* rp = repp ? repp : g_agg;         // fallback scratch (in-place safe)
    rp[(size_t)w * HD + j] = rep;

    float ti = t[w];
    float zi = g_z[w] / (g_deno[w] + 1e-8f); // deferred normalization

    float acc = sb1[j];
    #pragma unroll
    for (int k = 0; k < HD; k++)
        acc = fmaf(__shfl_sync(0xffffffffu, rep, k), sW1[k * HD + j], acc);
    acc = fmaf(ti, sW1[32 * HD + j], acc);
    acc = fmaf(zi, sW1[33 * HD + j], acc);
    acc = fmaxf(acc, 0.f);

    float o = acc * sW2[j];
    #pragma unroll
    for (int off = 16; off > 0; off >>= 1)
        o += __shfl_xor_sync(0xffffffffu, o, off);
    if (j == 0) outp[w] = o + sb2s[0];
    if (zoutp && j == 1) zoutp[w] = zi;
}

// ---------------- host ----------------
extern "C" void kernel_launch(void* const* d_in, const int* in_sizes, int n_in,
                              void* d_out, int out_size)
{
    const float* x     = (const float*)d_in[0];
    const float* t     = (const float*)d_in[1];
    const int*   row   = (const int*)  d_in[2];
    const int*   col   = (const int*)  d_in[3];
    const float* W_emb = (const float*)d_in[4];
    const float* b_emb = (const float*)d_in[5];
    const float* W_gcn = (const float*)d_in[6];
    const float* b_gcn = (const float*)d_in[7];
    const float* W1    = (const float*)d_in[8];
    const float* b1    = (const float*)d_in[9];
    const float* W2    = (const float*)d_in[10];
    const float* b2    = (const float*)d_in[11];

    int n  = in_sizes[1];          // t has N elements
    int e2 = in_sizes[2];          // full directed edge count
    int eh = e2 / 2;               // symmetric half

    float* outp = (float*)d_out;
    bool full = (out_size == 34 * n);
    float* repp  = full ? outp + n        : nullptr;
    float* zoutp = full ? outp + 33 * n   : nullptr;

    k_init   <<<2048, 256>>>(n);
    k_embed  <<<(n + 15) / 16, 256>>>(x, W_emb, b_emb, W_gcn, n);
    k_dotdeg <<<(eh + 127) / 128, 256>>>(row, col, eh);
    k_disscale<<<(n * HD + 255) / 256, 256>>>(n);
    k_expdeno<<<(eh + 255) / 256, 256>>>(row, col, t, eh);
    k_scatter<<<(2 * eh * 8 + 255) / 256, 256>>>(row, col, eh);   // launch idx 5 (ncu target)
    k_final  <<<(n + 7) / 8, 256>>>(t, W1, b1, W2, b2, b_gcn, outp, repp, zoutp, n);
}

// round 7
// speedup vs baseline: 1.5487x; 1.0209x over previous
#include <cuda_runtime.h>
#include <cstdint>

#define NMAX   100000
#define EHMAX  1600000
#define HD     32          // hidden dim (Hemb == Hgcn == 32)
#define NIN    128

// ---------------- device scratch (no allocations allowed) ----------------
__device__ __align__(16) float g_h  [NMAX * HD];   // relu(x@We + be)
__device__ __align__(16) float g_hw [NMAX * HD];   // dis * (h@Wg)   (dis-scaled!)
__device__ __align__(16) float g_agg[NMAX * HD];   // scatter target
__device__ float g_att [EHMAX];                    // per-undirected-edge raw dot
__device__ float g_deno[NMAX];
__device__ float g_z   [NMAX];                     // z NUMERATOR (divide in k_final)
__device__ float g_deg [NMAX];
__device__ float g_dis [NMAX];
__device__ unsigned g_amax_u;                      // ordered-uint encoded global max

// ordered monotone float<->uint mapping for atomicMax on floats
__device__ __forceinline__ unsigned henc(float f) {
    unsigned u = __float_as_uint(f);
    return (u & 0x80000000u) ? ~u : (u | 0x80000000u);
}
__device__ __forceinline__ float hdec(unsigned e) {
    return (e & 0x80000000u) ? __uint_as_float(e ^ 0x80000000u)
                             : __uint_as_float(~e);
}

// vectorized 16B reduction (no return) — 1 op replaces 4 scalar REDs
__device__ __forceinline__ void red_add_v4(float* p, float4 v) {
    asm volatile("red.global.add.v4.f32 [%0], {%1, %2, %3, %4};"
                 :: "l"(p), "f"(v.x), "f"(v.y), "f"(v.z), "f"(v.w)
                 : "memory");
}

// ---------------- K0: fused embed + small-array init ---------------------
// h = relu(x@We+be); hw = h@Wg.  Also zeroes deg/deno/z/amax (grid-stride).
__global__ __launch_bounds__(256) void k_embed(
    const float* __restrict__ x, const float* __restrict__ We,
    const float* __restrict__ be, const float* __restrict__ Wg, int n)
{
    // prologue: zero the small accumulators (consumers are in later kernels)
    {
        int gtid = blockIdx.x * 256 + threadIdx.x;
        int gstride = gridDim.x * 256;
        for (int i = gtid; i < n; i += gstride) {
            g_deg[i] = 0.f; g_deno[i] = 0.f; g_z[i] = 0.f;
        }
        if (gtid == 0) g_amax_u = 0x007fffffu;  // henc(-inf)
    }

    __shared__ float sWe[NIN * HD];
    __shared__ float sWg[HD * HD];
    __shared__ float sbe[HD];
    __shared__ float sx[8][2][NIN];

    int tid = threadIdx.x;
    for (int i = tid; i < NIN * HD; i += 256) sWe[i] = We[i];
    for (int i = tid; i < HD * HD;  i += 256) sWg[i] = Wg[i];
    if (tid < HD) sbe[tid] = be[tid];
    __syncthreads();

    int warp = tid >> 5, j = tid & 31;
    int n0 = (blockIdx.x * 8 + warp) * 2;
    int n1 = n0 + 1;
    bool v0 = n0 < n, v1 = n1 < n;

    if (v0) {
        const float* xr = x + (size_t)n0 * NIN;
        sx[warp][0][j] = xr[j]; sx[warp][0][j+32] = xr[j+32];
        sx[warp][0][j+64] = xr[j+64]; sx[warp][0][j+96] = xr[j+96];
    }
    if (v1) {
        const float* xr = x + (size_t)n1 * NIN;
        sx[warp][1][j] = xr[j]; sx[warp][1][j+32] = xr[j+32];
        sx[warp][1][j+64] = xr[j+64]; sx[warp][1][j+96] = xr[j+96];
    } else {
        sx[warp][1][j] = 0.f; sx[warp][1][j+32] = 0.f;
        sx[warp][1][j+64] = 0.f; sx[warp][1][j+96] = 0.f;
    }
    __syncwarp();
    if (!v0) return;

    float a0 = sbe[j], a1 = sbe[j];
    #pragma unroll
    for (int k = 0; k < NIN; k++) {
        float w = sWe[k * HD + j];
        a0 = fmaf(sx[warp][0][k], w, a0);
        a1 = fmaf(sx[warp][1][k], w, a1);
    }
    float h0 = fmaxf(a0, 0.f), h1 = fmaxf(a1, 0.f);
    g_h[n0 * HD + j] = h0;
    if (v1) g_h[n1 * HD + j] = h1;

    float c0 = 0.f, c1 = 0.f;
    #pragma unroll
    for (int k = 0; k < HD; k++) {
        float w = sWg[k * HD + j];
        c0 = fmaf(__shfl_sync(0xffffffffu, h0, k), w, c0);
        c1 = fmaf(__shfl_sync(0xffffffffu, h1, k), w, c1);
    }
    g_hw[n0 * HD + j] = c0;
    if (v1) g_hw[n1 * HD + j] = c1;
}

// ---------------- K1: att dot + global max + degree (fused) -------------
// 8 threads / edge, 4 edges / 8-thread group. Loads/stores guarded;
// shuffles UNCONDITIONAL (convergence-safe regardless of eh).
__global__ __launch_bounds__(256) void k_dotdeg(
    const int* __restrict__ row, const int* __restrict__ col, int eh)
{
    int g   = (blockIdx.x * blockDim.x + threadIdx.x) >> 3;
    int sub = threadIdx.x & 7;
    const float4* h4 = (const float4*)g_h;
    float lmax = -1e30f;
    int base = g * 4;
    #pragma unroll
    for (int q = 0; q < 4; q++) {
        int e = base + q;
        bool valid = (e < eh);
        float4 a = make_float4(0.f, 0.f, 0.f, 0.f);
        float4 b = a;
        int s = 0, d = 0;
        if (valid) {
            s = row[e]; d = col[e];
            a = h4[(size_t)s * 8 + sub];
            b = h4[(size_t)d * 8 + sub];
        }
        float p = a.x*b.x + a.y*b.y + a.z*b.z + a.w*b.w;
        p += __shfl_xor_sync(0xffffffffu, p, 4);
        p += __shfl_xor_sync(0xffffffffu, p, 2);
        p += __shfl_xor_sync(0xffffffffu, p, 1);
        if (valid) {
            if (sub == 0) { g_att[e] = p; atomicAdd(&g_deg[s], 1.f); }
            if (sub == 1) atomicAdd(&g_deg[d], 1.f);
            lmax = fmaxf(lmax, p);
        }
    }
    __shared__ float sm[256];
    sm[threadIdx.x] = lmax;
    __syncthreads();
    for (int s = 128; s > 0; s >>= 1) {
        if (threadIdx.x < s) sm[threadIdx.x] = fmaxf(sm[threadIdx.x], sm[threadIdx.x + s]);
        __syncthreads();
    }
    if (threadIdx.x == 0) atomicMax(&g_amax_u, henc(sm[0]));
}

// ---------------- K2: dis = rsqrt(deg+1); hw *= dis; agg = 0 (float4) ---
__global__ void k_disscale(int n) {
    int i = blockIdx.x * blockDim.x + threadIdx.x;   // float4 index
    if (i >= n * 8) return;
    int node = i >> 3;
    float dis = rsqrtf(g_deg[node] + 1.0f);
    if ((i & 7) == 0) g_dis[node] = dis;
    float4* hw4  = (float4*)g_hw;
    float4* agg4 = (float4*)g_agg;
    float4 v = hw4[i];
    v.x *= dis; v.y *= dis; v.z *= dis; v.w *= dis;
    hw4[i] = v;
    agg4[i] = make_float4(0.f, 0.f, 0.f, 0.f);
}

// ---------------- K3: fused scatter: messages + exp + deno + z ----------
// 16 threads / undirected edge: lanes 0-7 handle directed (s->d),
// lanes 8-15 handle (d->s). Slot-0 lane of each direction also does
// the attention-softmax accumulation for that direction.
__global__ __launch_bounds__(256) void k_scatter(
    const int* __restrict__ row, const int* __restrict__ col,
    const float* __restrict__ t, int eh)
{
    int gid = blockIdx.x * blockDim.x + threadIdx.x;
    int e   = gid >> 4;
    if (e >= eh) return;
    int lane16 = gid & 15;
    int sub    = lane16 & 7;          // float4 slot
    int flip   = lane16 >> 3;         // direction

    int s = row[e], d = col[e];
    int src = flip ? d : s;
    int dst = flip ? s : d;

    const float4* hw4 = (const float4*)g_hw;
    float4 v = hw4[(size_t)src * 8 + sub];          // already dis[src]*hw[src]
    red_add_v4(&g_agg[(size_t)dst * HD + sub * 4], v);

    if (sub == 0) {
        float amax = hdec(g_amax_u);
        float a = __expf(g_att[e] - amax);
        // directed edge (row=src, col=dst): deno[row]+=a ; z[row]+=a*t[col]
        atomicAdd(&g_deno[src], a);
        atomicAdd(&g_z[src], a * t[dst]);
    }
}

// ---------------- K4: gcn + residual + MLP head (warp per node) ----------
__global__ __launch_bounds__(256) void k_final(
    const float* __restrict__ t,
    const float* __restrict__ W1, const float* __restrict__ b1,
    const float* __restrict__ W2, const float* __restrict__ b2,
    const float* __restrict__ b_gcn,
    float* __restrict__ outp, float* __restrict__ repp, float* __restrict__ zoutp,
    int n)
{
    __shared__ float sW1[34 * HD];
    __shared__ float sb1[HD], sW2[HD], sb2s[1];
    int tid = threadIdx.x;
    for (int i = tid; i < 34 * HD; i += 256) sW1[i] = W1[i];
    if (tid < HD) { sb1[tid] = b1[tid]; sW2[tid] = W2[tid]; }
    if (tid == 0) sb2s[0] = b2[0];
    __syncthreads();

    int w = blockIdx.x * 8 + (tid >> 5);
    int j = tid & 31;
    if (w >= n) return;

    float dis  = g_dis[w];
    float dhwv = g_hw [(size_t)w * HD + j];   // dis*hw
    float aggv = g_agg[(size_t)w * HD + j];
    float gcn  = dis * aggv + dis * dhwv + b_gcn[j];  // dis*agg + dis^2*hw + b
    float rep  = g_h[(size_t)w * HD + j] + fmaxf(gcn, 0.f);

    float* rp = repp ? repp : g_agg;         // fallback scratch (in-place safe)
    rp[(size_t)w * HD + j] = rep;

    float ti = t[w];
    float zi = g_z[w] / (g_deno[w] + 1e-8f); // deferred normalization

    float acc = sb1[j];
    #pragma unroll
    for (int k = 0; k < HD; k++)
        acc = fmaf(__shfl_sync(0xffffffffu, rep, k), sW1[k * HD + j], acc);
    acc = fmaf(ti, sW1[32 * HD + j], acc);
    acc = fmaf(zi, sW1[33 * HD + j], acc);
    acc = fmaxf(acc, 0.f);

    float o = acc * sW2[j];
    #pragma unroll
    for (int off = 16; off > 0; off >>= 1)
        o += __shfl_xor_sync(0xffffffffu, o, off);
    if (j == 0) outp[w] = o + sb2s[0];
    if (zoutp && j == 1) zoutp[w] = zi;
}

// ---------------- host ----------------
extern "C" void kernel_launch(void* const* d_in, const int* in_sizes, int n_in,
                              void* d_out, int out_size)
{
    const float* x     = (const float*)d_in[0];
    const float* t     = (const float*)d_in[1];
    const int*   row   = (const int*)  d_in[2];
    const int*   col   = (const int*)  d_in[3];
    const float* W_emb = (const float*)d_in[4];
    const float* b_emb = (const float*)d_in[5];
    const float* W_gcn = (const float*)d_in[6];
    const float* b_gcn = (const float*)d_in[7];
    const float* W1    = (const float*)d_in[8];
    const float* b1    = (const float*)d_in[9];
    const float* W2    = (const float*)d_in[10];
    const float* b2    = (const float*)d_in[11];

    int n  = in_sizes[1];          // t has N elements
    int e2 = in_sizes[2];          // full directed edge count
    int eh = e2 / 2;               // symmetric half

    float* outp = (float*)d_out;
    bool full = (out_size == 34 * n);
    float* repp  = full ? outp + n        : nullptr;
    float* zoutp = full ? outp + 33 * n   : nullptr;

    k_embed   <<<(n + 15) / 16, 256>>>(x, W_emb, b_emb, W_gcn, n);  // idx 0 (+init)
    k_dotdeg  <<<(eh + 127) / 128, 256>>>(row, col, eh);            // idx 1
    k_disscale<<<(n * 8 + 255) / 256, 256>>>(n);                    // idx 2
    k_scatter <<<((size_t)eh * 16 + 255) / 256, 256>>>(row, col, t, eh); // idx 3 (ncu target)
    k_final   <<<(n + 7) / 8, 256>>>(t, W1, b1, W2, b2, b_gcn, outp, repp, zoutp, n);
}

// round 8
// speedup vs baseline: 1.6181x; 1.0448x over previous
#include <cuda_runtime.h>
#include <cstdint>

#define NMAX   100000
#define EHMAX  1600000
#define HD     32          // hidden dim (Hemb == Hgcn == 32)
#define NIN    128
#define NB     ((NMAX + 255) / 256)   // scan blocks (391)

// ---------------- device scratch (no allocations allowed) ----------------
__device__ __align__(16) float g_h  [NMAX * HD];   // relu(x@We + be)
__device__ __align__(16) float g_hw [NMAX * HD];   // dis * (h@Wg)  (pre-scaled)
__device__ float g_dis [NMAX];
__device__ int   g_cnt [NMAX];        // degree counts   (self-cleaned by k_gather)
__device__ int   g_rel [NMAX];        // fill cursors    (self-cleaned by k_gather)
__device__ int   g_loc [NMAX];        // per-block exclusive prefix
__device__ int   g_bsum[NB];          // block sums
__device__ int   g_bpre[NB];          // scanned block sums (exclusive)
__device__ int   g_adj [2 * EHMAX];   // CSR adjacency

// ---------------- K0: fused embed + degree count -------------------------
// h = relu(x@We+be); hw = h@Wg.  Also counts degrees (g_cnt zeroed by the
// previous call's k_gather; module load zero-initializes for call #1).
__global__ __launch_bounds__(256) void k_embed(
    const float* __restrict__ x, const float* __restrict__ We,
    const float* __restrict__ be, const float* __restrict__ Wg,
    const int* __restrict__ row, const int* __restrict__ col,
    int n, int eh)
{
    // prologue: degree counting over the undirected edge list
    {
        int gtid = blockIdx.x * 256 + threadIdx.x;
        int gstride = gridDim.x * 256;
        for (int e = gtid; e < eh; e += gstride) {
            atomicAdd(&g_cnt[row[e]], 1);
            atomicAdd(&g_cnt[col[e]], 1);
        }
    }

    __shared__ float sWe[NIN * HD];
    __shared__ float sWg[HD * HD];
    __shared__ float sbe[HD];
    __shared__ float sx[8][2][NIN];

    int tid = threadIdx.x;
    for (int i = tid; i < NIN * HD; i += 256) sWe[i] = We[i];
    for (int i = tid; i < HD * HD;  i += 256) sWg[i] = Wg[i];
    if (tid < HD) sbe[tid] = be[tid];
    __syncthreads();

    int warp = tid >> 5, j = tid & 31;
    int n0 = (blockIdx.x * 8 + warp) * 2;
    int n1 = n0 + 1;
    bool v0 = n0 < n, v1 = n1 < n;

    if (v0) {
        const float* xr = x + (size_t)n0 * NIN;
        sx[warp][0][j] = xr[j]; sx[warp][0][j+32] = xr[j+32];
        sx[warp][0][j+64] = xr[j+64]; sx[warp][0][j+96] = xr[j+96];
    }
    if (v1) {
        const float* xr = x + (size_t)n1 * NIN;
        sx[warp][1][j] = xr[j]; sx[warp][1][j+32] = xr[j+32];
        sx[warp][1][j+64] = xr[j+64]; sx[warp][1][j+96] = xr[j+96];
    } else {
        sx[warp][1][j] = 0.f; sx[warp][1][j+32] = 0.f;
        sx[warp][1][j+64] = 0.f; sx[warp][1][j+96] = 0.f;
    }
    __syncwarp();
    if (!v0) return;

    float a0 = sbe[j], a1 = sbe[j];
    #pragma unroll
    for (int k = 0; k < NIN; k++) {
        float w = sWe[k * HD + j];
        a0 = fmaf(sx[warp][0][k], w, a0);
        a1 = fmaf(sx[warp][1][k], w, a1);
    }
    float h0 = fmaxf(a0, 0.f), h1 = fmaxf(a1, 0.f);
    g_h[n0 * HD + j] = h0;
    if (v1) g_h[n1 * HD + j] = h1;

    float c0 = 0.f, c1 = 0.f;
    #pragma unroll
    for (int k = 0; k < HD; k++) {
        float w = sWg[k * HD + j];
        c0 = fmaf(__shfl_sync(0xffffffffu, h0, k), w, c0);
        c1 = fmaf(__shfl_sync(0xffffffffu, h1, k), w, c1);
    }
    g_hw[n0 * HD + j] = c0;
    if (v1) g_hw[n1 * HD + j] = c1;
}

// ---------------- K1: per-block exclusive scan of counts ----------------
__global__ void k_scan1(int n) {
    __shared__ int s[256];
    int t = threadIdx.x;
    int i = blockIdx.x * 256 + t;
    int v = (i < n) ? g_cnt[i] : 0;
    s[t] = v;
    __syncthreads();
    #pragma unroll
    for (int off = 1; off < 256; off <<= 1) {
        int xv = (t >= off) ? s[t - off] : 0;
        __syncthreads();
        s[t] += xv;
        __syncthreads();
    }
    if (i < n) g_loc[i] = s[t] - v;        // exclusive
    if (t == 255) g_bsum[blockIdx.x] = s[255];
}

// ---------------- K2: scan of block sums (single block) -----------------
__global__ void k_scan2(int nb) {
    __shared__ int s[512];
    int t = threadIdx.x;
    int v = (t < nb) ? g_bsum[t] : 0;
    s[t] = v;
    __syncthreads();
    #pragma unroll
    for (int off = 1; off < 512; off <<= 1) {
        int xv = (t >= off) ? s[t - off] : 0;
        __syncthreads();
        s[t] += xv;
        __syncthreads();
    }
    if (t < nb) g_bpre[t] = s[t] - v;      // exclusive
}

// ---------------- K3: CSR fill (atomic slot claim) ----------------------
__global__ void k_fill(const int* __restrict__ row, const int* __restrict__ col, int eh) {
    int e = blockIdx.x * blockDim.x + threadIdx.x;
    if (e >= eh) return;
    int s = row[e], d = col[e];
    int ps = g_loc[s] + g_bpre[s >> 8] + atomicAdd(&g_rel[s], 1);
    g_adj[ps] = d;
    int pd = g_loc[d] + g_bpre[d >> 8] + atomicAdd(&g_rel[d], 1);
    g_adj[pd] = s;
}

// ---------------- K4: dis = rsqrt(cnt+1); hw *= dis (float4) ------------
__global__ void k_disscale(int n) {
    int i = blockIdx.x * blockDim.x + threadIdx.x;   // float4 index
    if (i >= n * 8) return;
    int node = i >> 3;
    float dis = rsqrtf((float)g_cnt[node] + 1.0f);
    if ((i & 7) == 0) g_dis[node] = dis;
    float4* hw4 = (float4*)g_hw;
    float4 v = hw4[i];
    v.x *= dis; v.y *= dis; v.z *= dis; v.w *= dis;
    hw4[i] = v;
}

// ---------------- K5: fused gather (att softmax + z + GCN agg) + final --
// Warp per node. Lanes: sub = lane&7 (float4 slot), g = lane>>3 (one of 4
// neighbors in flight). Zero atomics; all accumulation in registers.
// exp() uses no global-max shift: z and att normalization are exactly
// shift-invariant, and raw dots are O(10) << 88 (fp32 exp overflow).
__global__ __launch_bounds__(256) void k_gather(
    const float* __restrict__ t,
    const float* __restrict__ W1, const float* __restrict__ b1,
    const float* __restrict__ W2, const float* __restrict__ b2,
    const float* __restrict__ b_gcn,
    float* __restrict__ outp, float* __restrict__ repp, float* __restrict__ zoutp,
    int n)
{
    __shared__ float sW1[34 * HD];
    __shared__ float sb1[HD], sW2[HD], sb2s[1];
    __shared__ float sAcc[8][128];            // per-warp float4 transpose buffer

    int tid = threadIdx.x;
    for (int i = tid; i < 34 * HD; i += 256) sW1[i] = W1[i];
    if (tid < HD) { sb1[tid] = b1[tid]; sW2[tid] = W2[tid]; }
    if (tid == 0) sb2s[0] = b2[0];
    __syncthreads();

    int warp = tid >> 5, lane = tid & 31;
    int node = blockIdx.x * 8 + warp;
    if (node >= n) return;

    int sub = lane & 7;
    int g   = lane >> 3;
    unsigned gmask = 0xFFu << (g * 8);

    const float4* h4  = (const float4*)g_h;
    const float4* hw4 = (const float4*)g_hw;

    float4 hi = h4[(size_t)node * 8 + sub];
    int off = g_loc[node] + g_bpre[node >> 8];
    int cnt = g_cnt[node];

    // self-clean CSR state for the next kernel_launch call
    if (lane == 0) { g_cnt[node] = 0; g_rel[node] = 0; }

    float4 acc = make_float4(0.f, 0.f, 0.f, 0.f);
    float deno = 0.f, z = 0.f;

    for (int k = g; k < cnt; k += 4) {
        int v = g_adj[off + k];
        float4 hv  = h4 [(size_t)v * 8 + sub];
        float4 hwv = hw4[(size_t)v * 8 + sub];
        float p = hi.x*hv.x + hi.y*hv.y + hi.z*hv.z + hi.w*hv.w;
        p += __shfl_xor_sync(gmask, p, 1);
        p += __shfl_xor_sync(gmask, p, 2);
        p += __shfl_xor_sync(gmask, p, 4);
        float a = __expf(p);
        deno += a;
        z = fmaf(a, t[v], z);
        acc.x += hwv.x; acc.y += hwv.y; acc.z += hwv.z; acc.w += hwv.w;
    }

    // deno/z: all 8 lanes of a group hold identical partials -> full-warp
    // tree sum = 8 * (sum over groups); *0.125f is exact (power of two).
    #pragma unroll
    for (int o = 1; o < 32; o <<= 1) {
        deno += __shfl_xor_sync(0xffffffffu, deno, o);
        z    += __shfl_xor_sync(0xffffffffu, z,    o);
    }
    deno *= 0.125f; z *= 0.125f;

    // transpose acc (float4-per-lane) -> scalar-per-feature via smem
    sAcc[warp][lane * 4 + 0] = acc.x;
    sAcc[warp][lane * 4 + 1] = acc.y;
    sAcc[warp][lane * 4 + 2] = acc.z;
    sAcc[warp][lane * 4 + 3] = acc.w;
    __syncwarp();
    int slot = lane >> 2, comp = lane & 3;
    float aggj = 0.f;
    #pragma unroll
    for (int gg = 0; gg < 4; gg++)
        aggj += sAcc[warp][(gg * 8 + slot) * 4 + comp];

    // ---- former k_final, inline ----
    float dis = g_dis[node];
    float hwj = g_hw[(size_t)node * HD + lane];   // = dis*hw
    float hj  = g_h [(size_t)node * HD + lane];
    float gcn = dis * aggj + dis * hwj + b_gcn[lane];
    float rep = hj + fmaxf(gcn, 0.f);
    if (repp) repp[(size_t)node * HD + lane] = rep;

    float zi = z / (deno + 1e-8f);
    float ti = t[node];

    float accm = sb1[lane];
    #pragma unroll
    for (int k = 0; k < HD; k++)
        accm = fmaf(__shfl_sync(0xffffffffu, rep, k), sW1[k * HD + lane], accm);
    accm = fmaf(ti, sW1[32 * HD + lane], accm);
    accm = fmaf(zi, sW1[33 * HD + lane], accm);
    accm = fmaxf(accm, 0.f);

    float o = accm * sW2[lane];
    #pragma unroll
    for (int offr = 16; offr > 0; offr >>= 1)
        o += __shfl_xor_sync(0xffffffffu, o, offr);
    if (lane == 0) outp[node] = o + sb2s[0];
    if (zoutp && lane == 1) zoutp[node] = zi;
}

// ---------------- host ----------------
extern "C" void kernel_launch(void* const* d_in, const int* in_sizes, int n_in,
                              void* d_out, int out_size)
{
    const float* x     = (const float*)d_in[0];
    const float* t     = (const float*)d_in[1];
    const int*   row   = (const int*)  d_in[2];
    const int*   col   = (const int*)  d_in[3];
    const float* W_emb = (const float*)d_in[4];
    const float* b_emb = (const float*)d_in[5];
    const float* W_gcn = (const float*)d_in[6];
    const float* b_gcn = (const float*)d_in[7];
    const float* W1    = (const float*)d_in[8];
    const float* b1    = (const float*)d_in[9];
    const float* W2    = (const float*)d_in[10];
    const float* b2    = (const float*)d_in[11];

    int n  = in_sizes[1];          // t has N elements
    int e2 = in_sizes[2];          // full directed edge count
    int eh = e2 / 2;               // symmetric half
    int nb = (n + 255) / 256;

    float* outp = (float*)d_out;
    bool full = (out_size == 34 * n);
    float* repp  = full ? outp + n      : nullptr;
    float* zoutp = full ? outp + 33 * n : nullptr;

    k_embed   <<<(n + 15) / 16, 256>>>(x, W_emb, b_emb, W_gcn, row, col, n, eh); // idx 0
    k_scan1   <<<nb, 256>>>(n);                                                  // idx 1
    k_scan2   <<<1, 512>>>(nb);                                                  // idx 2
    k_fill    <<<(eh + 255) / 256, 256>>>(row, col, eh);                         // idx 3 (ncu)
    k_disscale<<<(n * 8 + 255) / 256, 256>>>(n);                                 // idx 4
    k_gather  <<<(n + 7) / 8, 256>>>(t, W1, b1, W2, b2, b_gcn, outp, repp, zoutp, n); // idx 5
}

// round 9
// speedup vs baseline: 1.6870x; 1.0426x over previous
#include <cuda_runtime.h>
#include <cstdint>

#define NMAX   100000
#define EHMAX  1600000
#define HD     32          // hidden dim (Hemb == Hgcn == 32)
#define NIN    128
#define NB     ((NMAX + 255) / 256)   // scan blocks (391)

// ---------------- device scratch (no allocations allowed) ----------------
__device__ __align__(16) float g_h  [NMAX * HD];   // relu(x@We + be)
__device__ __align__(16) float g_hw [NMAX * HD];   // dis * (h@Wg)  (pre-scaled)
__device__ float g_dis [NMAX];
__device__ int   g_cnt [NMAX];        // degree counts   (self-cleaned by k_gather)
__device__ int   g_rel [NMAX];        // fill cursors    (self-cleaned by k_gather)
__device__ int   g_loc [NMAX];        // per-block exclusive prefix
__device__ int   g_bsum[NB];          // block sums
__device__ int   g_bpre[NB];          // scanned block sums (exclusive)
__device__ int   g_adj [2 * EHMAX];   // CSR adjacency

// ---------------- K0: fused embed + degree count -------------------------
__global__ __launch_bounds__(256) void k_embed(
    const float* __restrict__ x, const float* __restrict__ We,
    const float* __restrict__ be, const float* __restrict__ Wg,
    const int* __restrict__ row, const int* __restrict__ col,
    int n, int eh)
{
    // prologue: degree counting over the undirected edge list
    {
        int gtid = blockIdx.x * 256 + threadIdx.x;
        int gstride = gridDim.x * 256;
        for (int e = gtid; e < eh; e += gstride) {
            atomicAdd(&g_cnt[row[e]], 1);
            atomicAdd(&g_cnt[col[e]], 1);
        }
    }

    __shared__ float sWe[NIN * HD];
    __shared__ float sWg[HD * HD];
    __shared__ float sbe[HD];
    __shared__ float sx[8][2][NIN];

    int tid = threadIdx.x;
    for (int i = tid; i < NIN * HD; i += 256) sWe[i] = We[i];
    for (int i = tid; i < HD * HD;  i += 256) sWg[i] = Wg[i];
    if (tid < HD) sbe[tid] = be[tid];
    __syncthreads();

    int warp = tid >> 5, j = tid & 31;
    int n0 = (blockIdx.x * 8 + warp) * 2;
    int n1 = n0 + 1;
    bool v0 = n0 < n, v1 = n1 < n;

    if (v0) {
        const float* xr = x + (size_t)n0 * NIN;
        sx[warp][0][j] = xr[j]; sx[warp][0][j+32] = xr[j+32];
        sx[warp][0][j+64] = xr[j+64]; sx[warp][0][j+96] = xr[j+96];
    }
    if (v1) {
        const float* xr = x + (size_t)n1 * NIN;
        sx[warp][1][j] = xr[j]; sx[warp][1][j+32] = xr[j+32];
        sx[warp][1][j+64] = xr[j+64]; sx[warp][1][j+96] = xr[j+96];
    } else {
        sx[warp][1][j] = 0.f; sx[warp][1][j+32] = 0.f;
        sx[warp][1][j+64] = 0.f; sx[warp][1][j+96] = 0.f;
    }
    __syncwarp();
    if (!v0) return;

    float a0 = sbe[j], a1 = sbe[j];
    #pragma unroll
    for (int k = 0; k < NIN; k++) {
        float w = sWe[k * HD + j];
        a0 = fmaf(sx[warp][0][k], w, a0);
        a1 = fmaf(sx[warp][1][k], w, a1);
    }
    float h0 = fmaxf(a0, 0.f), h1 = fmaxf(a1, 0.f);
    g_h[n0 * HD + j] = h0;
    if (v1) g_h[n1 * HD + j] = h1;

    float c0 = 0.f, c1 = 0.f;
    #pragma unroll
    for (int k = 0; k < HD; k++) {
        float w = sWg[k * HD + j];
        c0 = fmaf(__shfl_sync(0xffffffffu, h0, k), w, c0);
        c1 = fmaf(__shfl_sync(0xffffffffu, h1, k), w, c1);
    }
    g_hw[n0 * HD + j] = c0;
    if (v1) g_hw[n1 * HD + j] = c1;
}

// ---------------- K1: per-block exclusive scan of counts ----------------
__global__ void k_scan1(int n) {
    __shared__ int s[256];
    int t = threadIdx.x;
    int i = blockIdx.x * 256 + t;
    int v = (i < n) ? g_cnt[i] : 0;
    s[t] = v;
    __syncthreads();
    #pragma unroll
    for (int off = 1; off < 256; off <<= 1) {
        int xv = (t >= off) ? s[t - off] : 0;
        __syncthreads();
        s[t] += xv;
        __syncthreads();
    }
    if (i < n) g_loc[i] = s[t] - v;        // exclusive
    if (t == 255) g_bsum[blockIdx.x] = s[255];
}

// ---------------- K2: scan of block sums (single block) -----------------
__global__ void k_scan2(int nb) {
    __shared__ int s[512];
    int t = threadIdx.x;
    int v = (t < nb) ? g_bsum[t] : 0;
    s[t] = v;
    __syncthreads();
    #pragma unroll
    for (int off = 1; off < 512; off <<= 1) {
        int xv = (t >= off) ? s[t - off] : 0;
        __syncthreads();
        s[t] += xv;
        __syncthreads();
    }
    if (t < nb) g_bpre[t] = s[t] - v;      // exclusive
}

// ---------------- K3: CSR fill (atomic slot claim) ----------------------
__global__ void k_fill(const int* __restrict__ row, const int* __restrict__ col, int eh) {
    int e = blockIdx.x * blockDim.x + threadIdx.x;
    if (e >= eh) return;
    int s = row[e], d = col[e];
    int ps = g_loc[s] + g_bpre[s >> 8] + atomicAdd(&g_rel[s], 1);
    g_adj[ps] = d;
    int pd = g_loc[d] + g_bpre[d >> 8] + atomicAdd(&g_rel[d], 1);
    g_adj[pd] = s;
}

// ---------------- K4: dis = rsqrt(cnt+1); hw *= dis (float4) ------------
__global__ void k_disscale(int n) {
    int i = blockIdx.x * blockDim.x + threadIdx.x;   // float4 index
    if (i >= n * 8) return;
    int node = i >> 3;
    float dis = rsqrtf((float)g_cnt[node] + 1.0f);
    if ((i & 7) == 0) g_dis[node] = dis;
    float4* hw4 = (float4*)g_hw;
    float4 v = hw4[i];
    v.x *= dis; v.y *= dis; v.z *= dis; v.w *= dis;
    hw4[i] = v;
}

// ---------------- K5: fused gather (att softmax + z + GCN agg) + final --
// Warp per node. sub = lane&7 (float4 slot), g = lane>>3 (neighbor group).
// Software-pipelined: 2 neighbors per group in flight (8 per warp) so the
// L2 gather latency (~250cyc) overlaps across independent chains.
__global__ __launch_bounds__(256) void k_gather(
    const float* __restrict__ t,
    const float* __restrict__ W1, const float* __restrict__ b1,
    const float* __restrict__ W2, const float* __restrict__ b2,
    const float* __restrict__ b_gcn,
    float* __restrict__ outp, float* __restrict__ repp, float* __restrict__ zoutp,
    int n)
{
    __shared__ float sW1[34 * HD];
    __shared__ float sb1[HD], sW2[HD], sb2s[1];
    __shared__ float sAcc[8][128];            // per-warp float4 transpose buffer

    int tid = threadIdx.x;
    for (int i = tid; i < 34 * HD; i += 256) sW1[i] = W1[i];
    if (tid < HD) { sb1[tid] = b1[tid]; sW2[tid] = W2[tid]; }
    if (tid == 0) sb2s[0] = b2[0];
    __syncthreads();

    int warp = tid >> 5, lane = tid & 31;
    int node = blockIdx.x * 8 + warp;
    if (node >= n) return;

    int sub = lane & 7;
    int g   = lane >> 3;
    unsigned gmask = 0xFFu << (g * 8);

    const float4* h4  = (const float4*)g_h;
    const float4* hw4 = (const float4*)g_hw;

    float4 hi = h4[(size_t)node * 8 + sub];
    int off = g_loc[node] + g_bpre[node >> 8];
    int cnt = g_cnt[node];

    // self-clean CSR state for the next kernel_launch call
    if (lane == 0) { g_cnt[node] = 0; g_rel[node] = 0; }

    float4 acc = make_float4(0.f, 0.f, 0.f, 0.f);
    float deno = 0.f, z = 0.f;

    int k = g;
    // pipelined: two independent neighbors per group per iteration
    for (; k + 4 < cnt; k += 8) {
        int v0 = g_adj[off + k];
        int v1 = g_adj[off + k + 4];
        float4 hv0  = h4 [(size_t)v0 * 8 + sub];
        float4 hv1  = h4 [(size_t)v1 * 8 + sub];
        float4 hwv0 = hw4[(size_t)v0 * 8 + sub];
        float4 hwv1 = hw4[(size_t)v1 * 8 + sub];
        float  t0   = t[v0];
        float  t1   = t[v1];

        float p0 = hi.x*hv0.x + hi.y*hv0.y + hi.z*hv0.z + hi.w*hv0.w;
        float p1 = hi.x*hv1.x + hi.y*hv1.y + hi.z*hv1.z + hi.w*hv1.w;
        p0 += __shfl_xor_sync(gmask, p0, 1);
        p1 += __shfl_xor_sync(gmask, p1, 1);
        p0 += __shfl_xor_sync(gmask, p0, 2);
        p1 += __shfl_xor_sync(gmask, p1, 2);
        p0 += __shfl_xor_sync(gmask, p0, 4);
        p1 += __shfl_xor_sync(gmask, p1, 4);
        float a0 = __expf(p0);
        float a1 = __expf(p1);
        deno += a0 + a1;
        z = fmaf(a0, t0, z);
        z = fmaf(a1, t1, z);
        acc.x += hwv0.x + hwv1.x;
        acc.y += hwv0.y + hwv1.y;
        acc.z += hwv0.z + hwv1.z;
        acc.w += hwv0.w + hwv1.w;
    }
    if (k < cnt) {  // at most one remainder per group
        int v = g_adj[off + k];
        float4 hv  = h4 [(size_t)v * 8 + sub];
        float4 hwv = hw4[(size_t)v * 8 + sub];
        float p = hi.x*hv.x + hi.y*hv.y + hi.z*hv.z + hi.w*hv.w;
        p += __shfl_xor_sync(gmask, p, 1);
        p += __shfl_xor_sync(gmask, p, 2);
        p += __shfl_xor_sync(gmask, p, 4);
        float a = __expf(p);
        deno += a;
        z = fmaf(a, t[v], z);
        acc.x += hwv.x; acc.y += hwv.y; acc.z += hwv.z; acc.w += hwv.w;
    }

    // deno/z: 8 lanes of each group hold identical partials -> warp tree
    // sum = 8 * (sum over groups); *0.125f is exact (power of two).
    #pragma unroll
    for (int o = 1; o < 32; o <<= 1) {
        deno += __shfl_xor_sync(0xffffffffu, deno, o);
        z    += __shfl_xor_sync(0xffffffffu, z,    o);
    }
    deno *= 0.125f; z *= 0.125f;

    // transpose acc (float4-per-lane) -> scalar-per-feature via smem
    sAcc[warp][lane * 4 + 0] = acc.x;
    sAcc[warp][lane * 4 + 1] = acc.y;
    sAcc[warp][lane * 4 + 2] = acc.z;
    sAcc[warp][lane * 4 + 3] = acc.w;
    __syncwarp();
    int slot = lane >> 2, comp = lane & 3;
    float aggj = 0.f;
    #pragma unroll
    for (int gg = 0; gg < 4; gg++)
        aggj += sAcc[warp][(gg * 8 + slot) * 4 + comp];

    // ---- former k_final, inline ----
    float dis = g_dis[node];
    float hwj = g_hw[(size_t)node * HD + lane];   // = dis*hw
    float hj  = g_h [(size_t)node * HD + lane];
    float gcn = dis * aggj + dis * hwj + b_gcn[lane];
    float rep = hj + fmaxf(gcn, 0.f);
    if (repp) repp[(size_t)node * HD + lane] = rep;

    float zi = z / (deno + 1e-8f);
    float ti = t[node];

    float accm = sb1[lane];
    #pragma unroll
    for (int kk = 0; kk < HD; kk++)
        accm = fmaf(__shfl_sync(0xffffffffu, rep, kk), sW1[kk * HD + lane], accm);
    accm = fmaf(ti, sW1[32 * HD + lane], accm);
    accm = fmaf(zi, sW1[33 * HD + lane], accm);
    accm = fmaxf(accm, 0.f);

    float o = accm * sW2[lane];
    #pragma unroll
    for (int offr = 16; offr > 0; offr >>= 1)
        o += __shfl_xor_sync(0xffffffffu, o, offr);
    if (lane == 0) outp[node] = o + sb2s[0];
    if (zoutp && lane == 1) zoutp[node] = zi;
}

// ---------------- host ----------------
extern "C" void kernel_launch(void* const* d_in, const int* in_sizes, int n_in,
                              void* d_out, int out_size)
{
    const float* x     = (const float*)d_in[0];
    const float* t     = (const float*)d_in[1];
    const int*   row   = (const int*)  d_in[2];
    const int*   col   = (const int*)  d_in[3];
    const float* W_emb = (const float*)d_in[4];
    const float* b_emb = (const float*)d_in[5];
    const float* W_gcn = (const float*)d_in[6];
    const float* b_gcn = (const float*)d_in[7];
    const float* W1    = (const float*)d_in[8];
    const float* b1    = (const float*)d_in[9];
    const float* W2    = (const float*)d_in[10];
    const float* b2    = (const float*)d_in[11];

    int n  = in_sizes[1];          // t has N elements
    int e2 = in_sizes[2];          // full directed edge count
    int eh = e2 / 2;               // symmetric half
    int nb = (n + 255) / 256;

    float* outp = (float*)d_out;
    bool full = (out_size == 34 * n);
    float* repp  = full ? outp + n      : nullptr;
    float* zoutp = full ? outp + 33 * n : nullptr;

    k_embed   <<<(n + 15) / 16, 256>>>(x, W_emb, b_emb, W_gcn, row, col, n, eh); // idx 0
    k_scan1   <<<nb, 256>>>(n);                                                  // idx 1
    k_scan2   <<<1, 512>>>(nb);                                                  // idx 2
    k_fill    <<<(eh + 255) / 256, 256>>>(row, col, eh);                         // idx 3 (ncu)
    k_disscale<<<(n * 8 + 255) / 256, 256>>>(n);                                 // idx 4
    k_gather  <<<(n + 7) / 8, 256>>>(t, W1, b1, W2, b2, b_gcn, outp, repp, zoutp, n); // idx 5
}